// round 14
// baseline (speedup 1.0000x reference)
#include <cuda_runtime.h>
#include <cuda_bf16.h>

#define NN   50000
#define NP   50176
#define NBLK 196
#define FIN  512
#define HID  128
#define CLS  64
#define NE   800000
#define EPSV 1e-5f

#define CS_BLKS   800
#define CNT_BLKS  256
#define PW_BLKS   192
#define FILL_BLKS 256
#define PG_BLKS   1568            // NP/32 (32-row tiles)

#define K1_CS0    0
#define K1_CNT0   (K1_CS0  + CS_BLKS)     // 800
#define K1_BN0    (K1_CNT0 + CNT_BLKS)    // 1056
#define K1_SCAN0  (K1_BN0  + 1)           // 1057
#define K1_PW0    (K1_SCAN0 + NBLK)       // 1253
#define K1_FILL0  (K1_PW0  + PW_BLKS)     // 1445
#define K1_PG0    (K1_FILL0 + FILL_BLKS)  // 1701
#define K1_BLOCKS (K1_PG0  + PG_BLKS)     // 3269

// ---------------- scratch (device globals) ------------------------------------
__device__ __align__(16) float    g_colsum[FIN];
__device__ __align__(16) float    g_colsq [FIN];
__device__ __align__(16) float    g_mu    [FIN];
__device__ __align__(16) float    g_rstd  [FIN];
__device__ int      g_cnt   [NP];
__device__ float    g_dinv  [NP];
__device__ int      g_rowstart[NP];
__device__ int      g_cursor  [NN];
__device__ int      g_esrc    [NE];
__device__ int      g_desc    [NBLK];

__device__ __align__(16) unsigned g_wp1 [HID * 16]; // word w bit l: k=4l+128(w>>2)+(w&3)
__device__ __align__(16) float    g_beta1[HID];
__device__ __align__(16) unsigned g_wp2 [CLS * 4];  // word w bit j: k=4j+w
__device__ __align__(16) float    g_beta2[CLS];

__device__ __align__(16) unsigned short g_h1b[NP * HID];
__device__ float    g_s1 [NP];
__device__ __align__(16) unsigned g_h2b[NP * CLS / 2];
__device__ float    g_s2 [NP];

// phase counters (reset by gather1 block 0 for next replay)
__device__ int g_cntdone, g_statsdone, g_scandone, g_bndone, g_pwdone;

__device__ __forceinline__ float bflo(unsigned w) { return __uint_as_float(w << 16); }
__device__ __forceinline__ float bfhi(unsigned w) { return __uint_as_float(w & 0xffff0000u); }

__device__ __forceinline__ void block_wait(int* ctr, int target)
{
    if (threadIdx.x == 0) {
        while (atomicAdd(ctr, 0) < target) __nanosleep(256);
        __threadfence();
    }
    __syncthreads();
}
__device__ __forceinline__ void block_arrive(int* ctr)
{
    __syncthreads();
    __threadfence();
    if (threadIdx.x == 0) atomicAdd(ctr, 1);
}

// ===================== K1: stats + CSR build + pack + GEMM1 ====================
__global__ void __launch_bounds__(512) K1(const int* __restrict__ edges,
                                          const float* __restrict__ x,
                                          const float* __restrict__ W1,
                                          const float* __restrict__ W2)
{
    int b = blockIdx.x;
    int t = threadIdx.x;
    int lane = t & 31, w = t >> 5;

    if (b < K1_CNT0) {
        // ---------------- colstats (800 blocks, 63 rows each) ----------------
        int r0 = b * 63;
        int r1 = r0 + 63; if (r1 > NN) r1 = NN;
        float s = 0.f, q = 0.f;
        const float* xc = x + t;
        for (int r = r0; r < r1; ++r) {
            float v = __ldg(&xc[(size_t)r * FIN]);
            s += v; q += v * v;
        }
        atomicAdd(&g_colsum[t], s);
        atomicAdd(&g_colsq [t], q);
        block_arrive(&g_statsdone);
        return;
    }
    if (b < K1_BN0) {
        // ---------------- degree count (grid-stride) ----------------
        int bb = b - K1_CNT0;
        if (bb == 0 && t < NBLK) g_desc[t] = 0;
        for (int e = bb * 512 + t; e < NE; e += CNT_BLKS * 512)
            atomicAdd(&g_cnt[edges[NE + e]], 1);
        block_arrive(&g_cntdone);
        return;
    }
    if (b < K1_SCAN0) {
        // ---------------- BN finalize (waits stats only) ----------------
        block_wait(&g_statsdone, CS_BLKS);
        float su = g_colsum[t], sq = g_colsq[t];
        float mu  = su * (1.f / NN);
        float var = sq * (1.f / NN) - mu * mu;
        g_mu[t]   = mu;
        g_rstd[t] = rsqrtf(var + EPSV);
        g_colsum[t] = 0.f;
        g_colsq [t] = 0.f;
        block_arrive(&g_bndone);
        return;
    }
    if (b < K1_PW0) {
        // ---------------- scan (decoupled lookback) ----------------
        int sb = b - K1_SCAN0;
        block_wait(&g_cntdone, CNT_BLKS);
        __shared__ int sp[256];
        __shared__ int spref;
        int v = 0;
        if (t < 256) { v = g_cnt[sb * 256 + t]; sp[t] = v; }
        __syncthreads();
        #pragma unroll
        for (int off = 1; off < 256; off <<= 1) {
            int u = (t >= off && t < 256) ? sp[t - off] : 0;
            __syncthreads();
            if (t < 256) sp[t] += u;
            __syncthreads();
        }
        if (t == 255) {
            int inc = sp[255];
            if (sb == 0) {
                atomicExch(&g_desc[0], (inc << 2) | 2);
                spref = 0;
            } else {
                atomicExch(&g_desc[sb], (inc << 2) | 1);
                int pre = 0, p = sb - 1;
                while (true) {
                    int d;
                    do { d = atomicAdd(&g_desc[p], 0); } while (!(d & 3));
                    pre += d >> 2;
                    if ((d & 3) == 2) break;
                    --p;
                }
                atomicExch(&g_desc[sb], ((pre + inc) << 2) | 2);
                spref = pre;
            }
        }
        __syncthreads();
        if (t < 256) {
            int idx = sb * 256 + t;
            int rs = sp[t] - v + spref;
            g_rowstart[idx] = rs;
            if (idx < NN) g_cursor[idx] = rs;
            g_dinv[idx] = rsqrtf((float)(v + 1));
            g_cnt[idx]  = 0;
        }
        block_arrive(&g_scandone);
        return;
    }
    if (b < K1_FILL0) {
        // ---------------- weight packing ----------------
        int bw = b - K1_PW0;                 // 0..191
        __shared__ float ssum[16];
        if (bw < HID) {
            int k = 4 * lane + 128 * (w >> 2) + (w & 3);
            float v = W1[k * HID + bw];
            unsigned bal = __ballot_sync(0xffffffffu, v > 0.f);
            if (lane == 0) g_wp1[bw * 16 + w] = bal;
            float av = fabsf(v);
            #pragma unroll
            for (int o = 16; o > 0; o >>= 1) av += __shfl_down_sync(0xffffffffu, av, o);
            if (lane == 0) ssum[w] = av;
            __syncthreads();
            if (t < 16) {
                float s = ssum[t];
                #pragma unroll
                for (int o = 8; o > 0; o >>= 1) s += __shfl_down_sync(0xffffu, s, o);
                if (t == 0) g_beta1[bw] = s * (1.f / FIN);
            }
        } else {
            int n = bw - HID;
            int k = 4 * lane + w;            // word w bit j -> k = 4j + w
            float v = (t < HID) ? W2[k * CLS + n] : 0.f;
            unsigned bal = __ballot_sync(0xffffffffu, v > 0.f);
            if (lane == 0 && w < 4) g_wp2[n * 4 + w] = bal;
            float av = fabsf(v);
            #pragma unroll
            for (int o = 16; o > 0; o >>= 1) av += __shfl_down_sync(0xffffffffu, av, o);
            if (lane == 0) ssum[w] = av;
            __syncthreads();
            if (t == 0)
                g_beta2[n] = (ssum[0] + ssum[1] + ssum[2] + ssum[3]) * (1.f / HID);
        }
        block_arrive(&g_pwdone);
        return;
    }
    if (b < K1_PG0) {
        // ---------------- CSR fill (grid-stride) ----------------
        int fb = b - K1_FILL0;
        block_wait(&g_scandone, NBLK);
        for (int e = fb * 512 + t; e < NE; e += FILL_BLKS * 512) {
            int row = edges[e];
            int col = edges[NE + e];
            int pos = atomicAdd(&g_cursor[col], 1);
            g_esrc[pos] = row;
        }
        return;
    }
    // ---------------- fused BinActive pack + popc GEMM1 (32-row tiles) --------
    {
        int pg = b - K1_PG0;
        block_wait(&g_bndone, 1);
        block_wait(&g_scandone, NBLK);
        block_wait(&g_pwdone, PW_BLKS);
        int m0 = pg * 32;

        __shared__ unsigned sA[32][16];

        #pragma unroll
        for (int rr = 0; rr < 2; ++rr) {
            int r = 2 * w + rr;
            int m = m0 + r;
            if (m < NN) {
                float ab = 0.f;
                const float4* xr4 = (const float4*)(x + (size_t)m * FIN);
                #pragma unroll
                for (int s = 0; s < 4; ++s) {
                    float4 xv  = __ldg(&xr4[lane + 32 * s]);
                    float4 muv = *(const float4*)&g_mu  [4 * lane + 128 * s];
                    float4 rsv = *(const float4*)&g_rstd[4 * lane + 128 * s];
                    float d0 = xv.x - muv.x, d1 = xv.y - muv.y;
                    float d2 = xv.z - muv.z, d3 = xv.w - muv.w;
                    unsigned b0 = __ballot_sync(0xffffffffu, d0 > 0.f);
                    unsigned b1 = __ballot_sync(0xffffffffu, d1 > 0.f);
                    unsigned b2 = __ballot_sync(0xffffffffu, d2 > 0.f);
                    unsigned b3 = __ballot_sync(0xffffffffu, d3 > 0.f);
                    if (lane == 0) {
                        sA[r][4 * s + 0] = b0; sA[r][4 * s + 1] = b1;
                        sA[r][4 * s + 2] = b2; sA[r][4 * s + 3] = b3;
                    }
                    ab += fabsf(d0) * rsv.x + fabsf(d1) * rsv.y
                        + fabsf(d2) * rsv.z + fabsf(d3) * rsv.w;
                }
                #pragma unroll
                for (int o = 16; o > 0; o >>= 1) ab += __shfl_down_sync(0xffffffffu, ab, o);
                if (lane == 0) g_s1[m] = ab * (1.f / FIN) * g_dinv[m];
            } else {
                if (lane < 16) sA[r][lane] = 0u;
            }
        }
        __syncthreads();

        int n  = t & 127;
        int rg = t >> 7;                      // 0..3, 8 rows each
        unsigned wr[16];
        #pragma unroll
        for (int i = 0; i < 16; ++i) wr[i] = g_wp1[n * 16 + i];
        #pragma unroll
        for (int k = 0; k < 8; ++k) {
            int r = rg * 8 + k;
            int acc = 0;
            #pragma unroll
            for (int i = 0; i < 16; ++i) acc += __popc(wr[i] ^ sA[r][i]);
            float fd = (float)(FIN - 2 * acc);
            g_h1b[(m0 + r) * HID + n] = __bfloat16_as_ushort(__float2bfloat16(fd));
        }
    }
}

// ================ gather1: warp-per-node, fused BinActive + GEMM2 ==============
__global__ void __launch_bounds__(256) k_gather1(const float* __restrict__ b1)
{
    int lane = threadIdx.x & 31;
    int i = blockIdx.x * 8 + (threadIdx.x >> 5);
    if (blockIdx.x == 0 && threadIdx.x == 0) {
        atomicExch(&g_cntdone, 0);  atomicExch(&g_statsdone, 0);
        atomicExch(&g_scandone, 0); atomicExch(&g_bndone, 0);
        atomicExch(&g_pwdone, 0);
    }
    const uint2* rows = (const uint2*)g_h1b;

    float a0, a1, a2, a3;
    {
        float sr = __ldg(&g_s1[i]);
        uint2 u = __ldg(&rows[i * 32 + lane]);
        a0 = sr * bflo(u.x);
        a1 = sr * bfhi(u.x);
        a2 = sr * bflo(u.y);
        a3 = sr * bfhi(u.y);
    }
    int s = g_rowstart[i], e = g_rowstart[i + 1];
    for (int base = s; base < e; base += 32) {
        int cnt = e - base; if (cnt > 32) cnt = 32;
        int idx = 0; float sv = 0.f;
        if (lane < cnt) { idx = __ldg(&g_esrc[base + lane]); sv = __ldg(&g_s1[idx]); }
        int k = 0;
        for (; k + 1 < cnt; k += 2) {
            int   r0 = __shfl_sync(0xffffffffu, idx, k);
            int   r1 = __shfl_sync(0xffffffffu, idx, k + 1);
            float q0 = __shfl_sync(0xffffffffu, sv, k);
            float q1 = __shfl_sync(0xffffffffu, sv, k + 1);
            uint2 u0 = __ldg(&rows[r0 * 32 + lane]);
            uint2 u1 = __ldg(&rows[r1 * 32 + lane]);
            a0 += q0 * bflo(u0.x) + q1 * bflo(u1.x);
            a1 += q0 * bfhi(u0.x) + q1 * bfhi(u1.x);
            a2 += q0 * bflo(u0.y) + q1 * bflo(u1.y);
            a3 += q0 * bfhi(u0.y) + q1 * bfhi(u1.y);
        }
        if (k < cnt) {
            int   r0 = __shfl_sync(0xffffffffu, idx, k);
            float q0 = __shfl_sync(0xffffffffu, sv, k);
            uint2 u0 = __ldg(&rows[r0 * 32 + lane]);
            a0 += q0 * bflo(u0.x);
            a1 += q0 * bfhi(u0.x);
            a2 += q0 * bflo(u0.y);
            a3 += q0 * bfhi(u0.y);
        }
    }

    float di = g_dinv[i];
    float4 bb = __ldg((const float4*)&b1[lane * 4]);
    float4 be = *(const float4*)&g_beta1[lane * 4];
    a0 = bb.x + di * be.x * a0;
    a1 = bb.y + di * be.y * a1;
    a2 = bb.z + di * be.z * a2;
    a3 = bb.w + di * be.w * a3;

    float av = fabsf(a0) + fabsf(a1) + fabsf(a2) + fabsf(a3);
    #pragma unroll
    for (int o = 16; o > 0; o >>= 1) av += __shfl_xor_sync(0xffffffffu, av, o);
    if (lane == 0) g_s2[i] = av * (1.f / HID) * di;

    unsigned x0 = __ballot_sync(0xffffffffu, a0 > 0.f);
    unsigned x1 = __ballot_sync(0xffffffffu, a1 > 0.f);
    unsigned x2 = __ballot_sync(0xffffffffu, a2 > 0.f);
    unsigned x3 = __ballot_sync(0xffffffffu, a3 > 0.f);

    uint4 wA = *(const uint4*)&g_wp2[(2 * lane) * 4];
    uint4 wB = *(const uint4*)&g_wp2[(2 * lane + 1) * 4];
    float d1 = (float)(HID - 2 * (__popc(wA.x ^ x0) + __popc(wA.y ^ x1)
                                + __popc(wA.z ^ x2) + __popc(wA.w ^ x3)));
    float d2 = (float)(HID - 2 * (__popc(wB.x ^ x0) + __popc(wB.y ^ x1)
                                + __popc(wB.z ^ x2) + __popc(wB.w ^ x3)));
    unsigned pk;
    asm("cvt.rn.bf16x2.f32 %0, %1, %2;" : "=r"(pk) : "f"(d2), "f"(d1));
    g_h2b[i * 32 + lane] = pk;
}

// ================ gather2: 4 edges/warp + fused log_softmax ====================
__global__ void __launch_bounds__(256) k_gather2_lsm(const float* __restrict__ b2,
                                                     float* __restrict__ out)
{
    int lane = threadIdx.x & 31;
    int i = blockIdx.x * 8 + (threadIdx.x >> 5);
    int grp = lane >> 3, j8 = lane & 7;
    const uint4* rows = (const uint4*)g_h2b;

    float a0, a1, a2, a3, a4, a5, a6, a7;
    {
        float sr = grp ? 0.f : __ldg(&g_s2[i]);
        uint4 u = __ldg(&rows[i * 8 + j8]);
        a0 = sr * bflo(u.x); a1 = sr * bfhi(u.x);
        a2 = sr * bflo(u.y); a3 = sr * bfhi(u.y);
        a4 = sr * bflo(u.z); a5 = sr * bfhi(u.z);
        a6 = sr * bflo(u.w); a7 = sr * bfhi(u.w);
    }
    int s = g_rowstart[i], e = g_rowstart[i + 1];
    for (int base = s; base < e; base += 32) {
        int cnt = e - base; if (cnt > 32) cnt = 32;
        int idx = 0; float sv = 0.f;
        if (lane < cnt) { idx = __ldg(&g_esrc[base + lane]); sv = __ldg(&g_s2[idx]); }
        for (int k = 0; k < cnt; k += 8) {
            int kk0 = k + grp, kk1 = k + 4 + grp;
            int   r0 = __shfl_sync(0xffffffffu, idx, kk0);
            float q0 = __shfl_sync(0xffffffffu, sv,  kk0);
            int   r1 = __shfl_sync(0xffffffffu, idx, kk1);
            float q1 = __shfl_sync(0xffffffffu, sv,  kk1);
            uint4 u0 = __ldg(&rows[r0 * 8 + j8]);
            uint4 u1 = __ldg(&rows[r1 * 8 + j8]);
            a0 += q0 * bflo(u0.x) + q1 * bflo(u1.x);
            a1 += q0 * bfhi(u0.x) + q1 * bfhi(u1.x);
            a2 += q0 * bflo(u0.y) + q1 * bflo(u1.y);
            a3 += q0 * bfhi(u0.y) + q1 * bfhi(u1.y);
            a4 += q0 * bflo(u0.z) + q1 * bflo(u1.z);
            a5 += q0 * bfhi(u0.z) + q1 * bfhi(u1.z);
            a6 += q0 * bflo(u0.w) + q1 * bflo(u1.w);
            a7 += q0 * bfhi(u0.w) + q1 * bfhi(u1.w);
        }
    }
    #pragma unroll
    for (int o = 8; o <= 16; o <<= 1) {
        a0 += __shfl_xor_sync(0xffffffffu, a0, o);
        a1 += __shfl_xor_sync(0xffffffffu, a1, o);
        a2 += __shfl_xor_sync(0xffffffffu, a2, o);
        a3 += __shfl_xor_sync(0xffffffffu, a3, o);
        a4 += __shfl_xor_sync(0xffffffffu, a4, o);
        a5 += __shfl_xor_sync(0xffffffffu, a5, o);
        a6 += __shfl_xor_sync(0xffffffffu, a6, o);
        a7 += __shfl_xor_sync(0xffffffffu, a7, o);
    }

    float di = g_dinv[i];
    float4 bbA = __ldg((const float4*)&b2[8 * j8]);
    float4 bbB = __ldg((const float4*)&b2[8 * j8 + 4]);
    float4 beA = *(const float4*)&g_beta2[8 * j8];
    float4 beB = *(const float4*)&g_beta2[8 * j8 + 4];
    a0 = bbA.x + di * beA.x * a0;  a1 = bbA.y + di * beA.y * a1;
    a2 = bbA.z + di * beA.z * a2;  a3 = bbA.w + di * beA.w * a3;
    a4 = bbB.x + di * beB.x * a4;  a5 = bbB.y + di * beB.y * a5;
    a6 = bbB.z + di * beB.z * a6;  a7 = bbB.w + di * beB.w * a7;

    float mx = fmaxf(fmaxf(fmaxf(a0, a1), fmaxf(a2, a3)),
                     fmaxf(fmaxf(a4, a5), fmaxf(a6, a7)));
    #pragma unroll
    for (int o = 4; o > 0; o >>= 1) mx = fmaxf(mx, __shfl_xor_sync(0xffffffffu, mx, o));
    float sum = expf(a0 - mx) + expf(a1 - mx) + expf(a2 - mx) + expf(a3 - mx)
              + expf(a4 - mx) + expf(a5 - mx) + expf(a6 - mx) + expf(a7 - mx);
    #pragma unroll
    for (int o = 4; o > 0; o >>= 1) sum += __shfl_xor_sync(0xffffffffu, sum, o);
    float l = mx + logf(sum);

    if (grp == 0) {
        float4* o4 = (float4*)(out + (size_t)i * CLS + 8 * j8);
        o4[0] = make_float4(a0 - l, a1 - l, a2 - l, a3 - l);
        o4[1] = make_float4(a4 - l, a5 - l, a6 - l, a7 - l);
    }
}

// ---------------- launch ---------------------------------------------------------
extern "C" void kernel_launch(void* const* d_in, const int* in_sizes, int n_in,
                              void* d_out, int out_size)
{
    const float* x     = (const float*)d_in[0];
    const int*   edges = (const int*)  d_in[1];
    const float* W1    = (const float*)d_in[2];
    const float* b1    = (const float*)d_in[3];
    const float* W2    = (const float*)d_in[4];
    const float* b2    = (const float*)d_in[5];
    float*       out   = (float*)d_out;

    K1<<<K1_BLOCKS, 512>>>(edges, x, W1, W2);
    k_gather1<<<NN / 8, 256>>>(b1);
    k_gather2_lsm<<<NN / 8, 256>>>(b2, out);
}

// round 15
// speedup vs baseline: 1.0963x; 1.0963x over previous
#include <cuda_runtime.h>
#include <cuda_bf16.h>

#define NN   50000
#define NP   50176
#define NBLK 196
#define FIN  512
#define HID  128
#define CLS  64
#define NE   800000
#define EPSV 1e-5f

#define CNT_BLKS  256
#define CS_BLKS   400
#define PW_BLKS   192
#define FILL_BLKS 256
#define PG_BLKS   1568            // NP/32 (32-row tiles)

#define K1_CNT0   0
#define K1_CS0    (K1_CNT0 + CNT_BLKS)    // 256
#define K1_SCAN0  (K1_CS0  + CS_BLKS)     // 656
#define K1_PW0    (K1_SCAN0 + NBLK)       // 852
#define K1_FILL0  (K1_PW0  + PW_BLKS)     // 1044
#define K1_PG0    (K1_FILL0 + FILL_BLKS)  // 1300
#define K1_BLOCKS (K1_PG0  + PG_BLKS)     // 2868

// ---------------- scratch (device globals) ------------------------------------
__device__ __align__(16) float    g_colsum[FIN];
__device__ __align__(16) float    g_colsq [FIN];
__device__ __align__(16) float    g_mu    [FIN];
__device__ __align__(16) float    g_rstd  [FIN];
__device__ int      g_cnt   [NP];
__device__ float    g_dinv  [NP];
__device__ int      g_rowstart[NP];
__device__ int      g_cursor  [NN];
__device__ int      g_esrc    [NE];
__device__ int      g_desc    [NBLK];

__device__ __align__(16) unsigned g_wp1 [HID * 16]; // word w bit l: k=4l+128(w>>2)+(w&3)
__device__ __align__(16) float    g_beta1[HID];
__device__ __align__(16) unsigned g_wp2 [CLS * 4];  // word w bit j: k=4j+w
__device__ __align__(16) float    g_beta2[CLS];

__device__ __align__(16) unsigned short g_h1b[NP * HID];
__device__ float    g_s1 [NP];
__device__ __align__(16) unsigned g_h2b[NP * CLS / 2];
__device__ float    g_s2 [NP];

// phase counters (reset by gather1 block 0 for next replay)
__device__ int g_cntdone, g_statsdone, g_scandone, g_bndone, g_pwdone;

__device__ __forceinline__ float bflo(unsigned w) { return __uint_as_float(w << 16); }
__device__ __forceinline__ float bfhi(unsigned w) { return __uint_as_float(w & 0xffff0000u); }

__device__ __forceinline__ void block_wait(int* ctr, int target)
{
    if (threadIdx.x == 0) {
        while (atomicAdd(ctr, 0) < target) __nanosleep(256);
        __threadfence();
    }
    __syncthreads();
}
__device__ __forceinline__ void block_arrive(int* ctr)
{
    __syncthreads();
    __threadfence();
    if (threadIdx.x == 0) atomicAdd(ctr, 1);
}

// ===================== K1: CSR build + stats + pack + GEMM1 ====================
__global__ void __launch_bounds__(512) K1(const int* __restrict__ edges,
                                          const float* __restrict__ x,
                                          const float* __restrict__ W1,
                                          const float* __restrict__ W2)
{
    int b = blockIdx.x;
    int t = threadIdx.x;
    int lane = t & 31, w = t >> 5;

    if (b < K1_CS0) {
        // ---------------- degree count (first in dispatch order) --------------
        if (b == 0 && t < NBLK) g_desc[t] = 0;
        for (int e = b * 512 + t; e < NE; e += CNT_BLKS * 512)
            atomicAdd(&g_cnt[edges[NE + e]], 1);
        block_arrive(&g_cntdone);
        return;
    }
    if (b < K1_SCAN0) {
        // ---------------- colstats ----------------
        int bb = b - K1_CS0;
        int r0 = bb * 125;
        int r1 = r0 + 125; if (r1 > NN) r1 = NN;
        float s = 0.f, q = 0.f;
        const float* xc = x + t;
        for (int r = r0; r < r1; ++r) {
            float v = __ldg(&xc[(size_t)r * FIN]);
            s += v; q += v * v;
        }
        atomicAdd(&g_colsum[t], s);
        atomicAdd(&g_colsq [t], q);
        block_arrive(&g_statsdone);
        return;
    }
    if (b < K1_PW0) {
        // ---------------- scan (decoupled lookback) + BN finalize -------------
        int sb = b - K1_SCAN0;
        block_wait(&g_cntdone, CNT_BLKS);
        __shared__ int sp[256];
        __shared__ int spref;
        int v = 0;
        if (t < 256) { v = g_cnt[sb * 256 + t]; sp[t] = v; }
        __syncthreads();
        #pragma unroll
        for (int off = 1; off < 256; off <<= 1) {
            int u = (t >= off && t < 256) ? sp[t - off] : 0;
            __syncthreads();
            if (t < 256) sp[t] += u;
            __syncthreads();
        }
        if (t == 255) {
            int inc = sp[255];
            if (sb == 0) {
                atomicExch(&g_desc[0], (inc << 2) | 2);
                spref = 0;
            } else {
                atomicExch(&g_desc[sb], (inc << 2) | 1);
                int pre = 0, p = sb - 1;
                while (true) {
                    int d;
                    do { d = atomicAdd(&g_desc[p], 0); } while (!(d & 3));
                    pre += d >> 2;
                    if ((d & 3) == 2) break;
                    --p;
                }
                atomicExch(&g_desc[sb], ((pre + inc) << 2) | 2);
                spref = pre;
            }
        }
        __syncthreads();
        if (t < 256) {
            int idx = sb * 256 + t;
            int rs = sp[t] - v + spref;
            g_rowstart[idx] = rs;
            if (idx < NN) g_cursor[idx] = rs;
            g_dinv[idx] = rsqrtf((float)(v + 1));
            g_cnt[idx]  = 0;
        }
        block_arrive(&g_scandone);
        if (sb == 0) {
            block_wait(&g_statsdone, CS_BLKS);
            float su = g_colsum[t], sq = g_colsq[t];
            float mu  = su * (1.f / NN);
            float var = sq * (1.f / NN) - mu * mu;
            g_mu[t]   = mu;
            g_rstd[t] = rsqrtf(var + EPSV);
            g_colsum[t] = 0.f;
            g_colsq [t] = 0.f;
            block_arrive(&g_bndone);
        }
        return;
    }
    if (b < K1_FILL0) {
        // ---------------- weight packing ----------------
        int bw = b - K1_PW0;                 // 0..191
        __shared__ float ssum[16];
        if (bw < HID) {
            int k = 4 * lane + 128 * (w >> 2) + (w & 3);
            float v = W1[k * HID + bw];
            unsigned bal = __ballot_sync(0xffffffffu, v > 0.f);
            if (lane == 0) g_wp1[bw * 16 + w] = bal;
            float av = fabsf(v);
            #pragma unroll
            for (int o = 16; o > 0; o >>= 1) av += __shfl_down_sync(0xffffffffu, av, o);
            if (lane == 0) ssum[w] = av;
            __syncthreads();
            if (t < 16) {
                float s = ssum[t];
                #pragma unroll
                for (int o = 8; o > 0; o >>= 1) s += __shfl_down_sync(0xffffu, s, o);
                if (t == 0) g_beta1[bw] = s * (1.f / FIN);
            }
        } else {
            int n = bw - HID;
            int k = 4 * lane + w;            // word w bit j -> k = 4j + w
            float v = (t < HID) ? W2[k * CLS + n] : 0.f;
            unsigned bal = __ballot_sync(0xffffffffu, v > 0.f);
            if (lane == 0 && w < 4) g_wp2[n * 4 + w] = bal;
            float av = fabsf(v);
            #pragma unroll
            for (int o = 16; o > 0; o >>= 1) av += __shfl_down_sync(0xffffffffu, av, o);
            if (lane == 0) ssum[w] = av;
            __syncthreads();
            if (t == 0)
                g_beta2[n] = (ssum[0] + ssum[1] + ssum[2] + ssum[3]) * (1.f / HID);
        }
        block_arrive(&g_pwdone);
        return;
    }
    if (b < K1_PG0) {
        // ---------------- CSR fill (grid-stride) ----------------
        int fb = b - K1_FILL0;
        block_wait(&g_scandone, NBLK);
        for (int e = fb * 512 + t; e < NE; e += FILL_BLKS * 512) {
            int row = edges[e];
            int col = edges[NE + e];
            int pos = atomicAdd(&g_cursor[col], 1);
            g_esrc[pos] = row;
        }
        return;
    }
    // ------ fused BinActive pack + popc GEMM1 (32-row tiles, REVERSE order) ---
    {
        int pg = PG_BLKS - 1 - (b - K1_PG0);   // early blocks take the LAST rows
        block_wait(&g_bndone, 1);
        block_wait(&g_pwdone, PW_BLKS);
        int m0 = pg * 32;

        __shared__ unsigned sA[32][16];

        #pragma unroll
        for (int rr = 0; rr < 2; ++rr) {
            int r = 2 * w + rr;
            int m = m0 + r;
            if (m < NN) {
                float ab = 0.f;
                const float4* xr4 = (const float4*)(x + (size_t)m * FIN);
                #pragma unroll
                for (int s = 0; s < 4; ++s) {
                    float4 xv  = __ldg(&xr4[lane + 32 * s]);
                    float4 muv = *(const float4*)&g_mu  [4 * lane + 128 * s];
                    float4 rsv = *(const float4*)&g_rstd[4 * lane + 128 * s];
                    float d0 = xv.x - muv.x, d1 = xv.y - muv.y;
                    float d2 = xv.z - muv.z, d3 = xv.w - muv.w;
                    unsigned b0 = __ballot_sync(0xffffffffu, d0 > 0.f);
                    unsigned b1 = __ballot_sync(0xffffffffu, d1 > 0.f);
                    unsigned b2 = __ballot_sync(0xffffffffu, d2 > 0.f);
                    unsigned b3 = __ballot_sync(0xffffffffu, d3 > 0.f);
                    if (lane == 0) {
                        sA[r][4 * s + 0] = b0; sA[r][4 * s + 1] = b1;
                        sA[r][4 * s + 2] = b2; sA[r][4 * s + 3] = b3;
                    }
                    ab += fabsf(d0) * rsv.x + fabsf(d1) * rsv.y
                        + fabsf(d2) * rsv.z + fabsf(d3) * rsv.w;
                }
                #pragma unroll
                for (int o = 16; o > 0; o >>= 1) ab += __shfl_down_sync(0xffffffffu, ab, o);
                if (lane == 0) g_s1[m] = ab * (1.f / FIN) * g_dinv[m];
            } else {
                if (lane < 16) sA[r][lane] = 0u;
            }
        }
        __syncthreads();

        int n  = t & 127;
        int rg = t >> 7;                      // 0..3, 8 rows each
        unsigned wr[16];
        #pragma unroll
        for (int i = 0; i < 16; ++i) wr[i] = g_wp1[n * 16 + i];
        #pragma unroll
        for (int k = 0; k < 8; ++k) {
            int r = rg * 8 + k;
            int acc = 0;
            #pragma unroll
            for (int i = 0; i < 16; ++i) acc += __popc(wr[i] ^ sA[r][i]);
            float fd = (float)(FIN - 2 * acc);
            g_h1b[(m0 + r) * HID + n] = __bfloat16_as_ushort(__float2bfloat16(fd));
        }
    }
}

// ================ gather1: warp-per-node, fused BinActive + GEMM2 ==============
__global__ void __launch_bounds__(256) k_gather1(const float* __restrict__ b1)
{
    int lane = threadIdx.x & 31;
    int i = blockIdx.x * 8 + (threadIdx.x >> 5);
    if (blockIdx.x == 0 && threadIdx.x == 0) {
        atomicExch(&g_cntdone, 0);  atomicExch(&g_statsdone, 0);
        atomicExch(&g_scandone, 0); atomicExch(&g_bndone, 0);
        atomicExch(&g_pwdone, 0);
    }
    const uint2* rows = (const uint2*)g_h1b;

    float a0, a1, a2, a3;
    {
        float sr = __ldg(&g_s1[i]);
        uint2 u = __ldg(&rows[i * 32 + lane]);
        a0 = sr * bflo(u.x);
        a1 = sr * bfhi(u.x);
        a2 = sr * bflo(u.y);
        a3 = sr * bfhi(u.y);
    }
    int s = g_rowstart[i], e = g_rowstart[i + 1];
    for (int base = s; base < e; base += 32) {
        int cnt = e - base; if (cnt > 32) cnt = 32;
        int idx = 0; float sv = 0.f;
        if (lane < cnt) { idx = __ldg(&g_esrc[base + lane]); sv = __ldg(&g_s1[idx]); }
        int k = 0;
        for (; k + 1 < cnt; k += 2) {
            int   r0 = __shfl_sync(0xffffffffu, idx, k);
            int   r1 = __shfl_sync(0xffffffffu, idx, k + 1);
            float q0 = __shfl_sync(0xffffffffu, sv, k);
            float q1 = __shfl_sync(0xffffffffu, sv, k + 1);
            uint2 u0 = __ldg(&rows[r0 * 32 + lane]);
            uint2 u1 = __ldg(&rows[r1 * 32 + lane]);
            a0 += q0 * bflo(u0.x) + q1 * bflo(u1.x);
            a1 += q0 * bfhi(u0.x) + q1 * bfhi(u1.x);
            a2 += q0 * bflo(u0.y) + q1 * bflo(u1.y);
            a3 += q0 * bfhi(u0.y) + q1 * bfhi(u1.y);
        }
        if (k < cnt) {
            int   r0 = __shfl_sync(0xffffffffu, idx, k);
            float q0 = __shfl_sync(0xffffffffu, sv, k);
            uint2 u0 = __ldg(&rows[r0 * 32 + lane]);
            a0 += q0 * bflo(u0.x);
            a1 += q0 * bfhi(u0.x);
            a2 += q0 * bflo(u0.y);
            a3 += q0 * bfhi(u0.y);
        }
    }

    float di = g_dinv[i];
    float4 bb = __ldg((const float4*)&b1[lane * 4]);
    float4 be = *(const float4*)&g_beta1[lane * 4];
    a0 = bb.x + di * be.x * a0;
    a1 = bb.y + di * be.y * a1;
    a2 = bb.z + di * be.z * a2;
    a3 = bb.w + di * be.w * a3;

    float av = fabsf(a0) + fabsf(a1) + fabsf(a2) + fabsf(a3);
    #pragma unroll
    for (int o = 16; o > 0; o >>= 1) av += __shfl_xor_sync(0xffffffffu, av, o);
    if (lane == 0) g_s2[i] = av * (1.f / HID) * di;

    unsigned x0 = __ballot_sync(0xffffffffu, a0 > 0.f);
    unsigned x1 = __ballot_sync(0xffffffffu, a1 > 0.f);
    unsigned x2 = __ballot_sync(0xffffffffu, a2 > 0.f);
    unsigned x3 = __ballot_sync(0xffffffffu, a3 > 0.f);

    uint4 wA = *(const uint4*)&g_wp2[(2 * lane) * 4];
    uint4 wB = *(const uint4*)&g_wp2[(2 * lane + 1) * 4];
    float d1 = (float)(HID - 2 * (__popc(wA.x ^ x0) + __popc(wA.y ^ x1)
                                + __popc(wA.z ^ x2) + __popc(wA.w ^ x3)));
    float d2 = (float)(HID - 2 * (__popc(wB.x ^ x0) + __popc(wB.y ^ x1)
                                + __popc(wB.z ^ x2) + __popc(wB.w ^ x3)));
    unsigned pk;
    asm("cvt.rn.bf16x2.f32 %0, %1, %2;" : "=r"(pk) : "f"(d2), "f"(d1));
    g_h2b[i * 32 + lane] = pk;
}

// ================ gather2: 4 edges/warp + fused log_softmax ====================
__global__ void __launch_bounds__(256) k_gather2_lsm(const float* __restrict__ b2,
                                                     float* __restrict__ out)
{
    int lane = threadIdx.x & 31;
    int i = blockIdx.x * 8 + (threadIdx.x >> 5);
    int grp = lane >> 3, j8 = lane & 7;
    const uint4* rows = (const uint4*)g_h2b;

    float a0, a1, a2, a3, a4, a5, a6, a7;
    {
        float sr = grp ? 0.f : __ldg(&g_s2[i]);
        uint4 u = __ldg(&rows[i * 8 + j8]);
        a0 = sr * bflo(u.x); a1 = sr * bfhi(u.x);
        a2 = sr * bflo(u.y); a3 = sr * bfhi(u.y);
        a4 = sr * bflo(u.z); a5 = sr * bfhi(u.z);
        a6 = sr * bflo(u.w); a7 = sr * bfhi(u.w);
    }
    int s = g_rowstart[i], e = g_rowstart[i + 1];
    for (int base = s; base < e; base += 32) {
        int cnt = e - base; if (cnt > 32) cnt = 32;
        int idx = 0; float sv = 0.f;
        if (lane < cnt) { idx = __ldg(&g_esrc[base + lane]); sv = __ldg(&g_s2[idx]); }
        for (int k = 0; k < cnt; k += 8) {
            int kk0 = k + grp, kk1 = k + 4 + grp;
            int   r0 = __shfl_sync(0xffffffffu, idx, kk0);
            float q0 = __shfl_sync(0xffffffffu, sv,  kk0);
            int   r1 = __shfl_sync(0xffffffffu, idx, kk1);
            float q1 = __shfl_sync(0xffffffffu, sv,  kk1);
            uint4 u0 = __ldg(&rows[r0 * 8 + j8]);
            uint4 u1 = __ldg(&rows[r1 * 8 + j8]);
            a0 += q0 * bflo(u0.x) + q1 * bflo(u1.x);
            a1 += q0 * bfhi(u0.x) + q1 * bfhi(u1.x);
            a2 += q0 * bflo(u0.y) + q1 * bflo(u1.y);
            a3 += q0 * bfhi(u0.y) + q1 * bfhi(u1.y);
            a4 += q0 * bflo(u0.z) + q1 * bflo(u1.z);
            a5 += q0 * bfhi(u0.z) + q1 * bfhi(u1.z);
            a6 += q0 * bflo(u0.w) + q1 * bflo(u1.w);
            a7 += q0 * bfhi(u0.w) + q1 * bfhi(u1.w);
        }
    }
    #pragma unroll
    for (int o = 8; o <= 16; o <<= 1) {
        a0 += __shfl_xor_sync(0xffffffffu, a0, o);
        a1 += __shfl_xor_sync(0xffffffffu, a1, o);
        a2 += __shfl_xor_sync(0xffffffffu, a2, o);
        a3 += __shfl_xor_sync(0xffffffffu, a3, o);
        a4 += __shfl_xor_sync(0xffffffffu, a4, o);
        a5 += __shfl_xor_sync(0xffffffffu, a5, o);
        a6 += __shfl_xor_sync(0xffffffffu, a6, o);
        a7 += __shfl_xor_sync(0xffffffffu, a7, o);
    }

    float di = g_dinv[i];
    float4 bbA = __ldg((const float4*)&b2[8 * j8]);
    float4 bbB = __ldg((const float4*)&b2[8 * j8 + 4]);
    float4 beA = *(const float4*)&g_beta2[8 * j8];
    float4 beB = *(const float4*)&g_beta2[8 * j8 + 4];
    a0 = bbA.x + di * beA.x * a0;  a1 = bbA.y + di * beA.y * a1;
    a2 = bbA.z + di * beA.z * a2;  a3 = bbA.w + di * beA.w * a3;
    a4 = bbB.x + di * beB.x * a4;  a5 = bbB.y + di * beB.y * a5;
    a6 = bbB.z + di * beB.z * a6;  a7 = bbB.w + di * beB.w * a7;

    float mx = fmaxf(fmaxf(fmaxf(a0, a1), fmaxf(a2, a3)),
                     fmaxf(fmaxf(a4, a5), fmaxf(a6, a7)));
    #pragma unroll
    for (int o = 4; o > 0; o >>= 1) mx = fmaxf(mx, __shfl_xor_sync(0xffffffffu, mx, o));
    float sum = expf(a0 - mx) + expf(a1 - mx) + expf(a2 - mx) + expf(a3 - mx)
              + expf(a4 - mx) + expf(a5 - mx) + expf(a6 - mx) + expf(a7 - mx);
    #pragma unroll
    for (int o = 4; o > 0; o >>= 1) sum += __shfl_xor_sync(0xffffffffu, sum, o);
    float l = mx + logf(sum);

    if (grp == 0) {
        float4* o4 = (float4*)(out + (size_t)i * CLS + 8 * j8);
        o4[0] = make_float4(a0 - l, a1 - l, a2 - l, a3 - l);
        o4[1] = make_float4(a4 - l, a5 - l, a6 - l, a7 - l);
    }
}

// ---------------- launch ---------------------------------------------------------
extern "C" void kernel_launch(void* const* d_in, const int* in_sizes, int n_in,
                              void* d_out, int out_size)
{
    const float* x     = (const float*)d_in[0];
    const int*   edges = (const int*)  d_in[1];
    const float* W1    = (const float*)d_in[2];
    const float* b1    = (const float*)d_in[3];
    const float* W2    = (const float*)d_in[4];
    const float* b2    = (const float*)d_in[5];
    float*       out   = (float*)d_out;

    K1<<<K1_BLOCKS, 512>>>(edges, x, W1, W2);
    k_gather1<<<NN / 8, 256>>>(b1);
    k_gather2_lsm<<<NN / 8, 256>>>(b2, out);
}